// round 15
// baseline (speedup 1.0000x reference)
#include <cuda_runtime.h>

// out[n,m,:4] = relu( zw4[n] + xwb4[m] ),  zw4 = z@W1, xwb4 = x^T@W2 + b
// N=8192, M=128, DZ=DX=128, H=4.
//
// R13 skeleton (best: 9.6us kernel) + ONE change: the output stream uses
// 256-bit stores (st.global.v8.f32, Blackwell) -> 8 STG.256/thread instead
// of 16 STG.128. Lane writes consecutive m pairs {2l,2l+1} and {64+2l,65+2l}.

#define N_ROWS   8192
#define M_COLS   128
#define D_Z      128
#define D_X      128
#define NBLOCKS  148
#define NTHREADS 512
#define NWARPS   (NTHREADS / 32)       // 16

#define STG256(PTR, A, B)                                            \
    asm volatile("st.global.v8.f32 [%0], {%1,%2,%3,%4,%5,%6,%7,%8};" \
        :: "l"(PTR), "f"((A).x), "f"((A).y), "f"((A).z), "f"((A).w), \
           "f"((B).x), "f"((B).y), "f"((B).z), "f"((B).w) : "memory")

__global__ __launch_bounds__(NTHREADS)
void fused_kernel(const float* __restrict__ z,
                  const float* __restrict__ x,
                  const float* __restrict__ W,
                  const float* __restrict__ b,
                  float4* __restrict__ out4)
{
    __shared__ float4 sPart[NWARPS][M_COLS];   // 32 KB xwb partials
    __shared__ float4 sXWB[M_COLS];            // 2 KB

    const int tid  = threadIdx.x;
    const int bid  = blockIdx.x;
    const int lane = tid & 31;
    const int warp = tid >> 5;                 // 0..15
    const float4* W4 = reinterpret_cast<const float4*>(W);
    const float4* x4 = reinterpret_cast<const float4*>(x);

    // Row range for this block (55/56 rows); warp owns 4 consecutive rows.
    const int r0 = (bid * N_ROWS) / NBLOCKS;
    const int r1 = ((bid + 1) * N_ROWS) / NBLOCKS;
    const int base_row = r0 + warp * 4;

    // ---- 1) Issue z loads for this warp's (up to) 4 rows first (DRAM) ----
    int   rown[4];
    bool  valid[4];
    float4 zv[4];
    #pragma unroll
    for (int j = 0; j < 4; ++j) {
        rown[j]  = base_row + j;
        valid[j] = rown[j] < r1;
        const int safe = valid[j] ? rown[j] : (r1 - 1);   // in-bounds clamp
        zv[j] = reinterpret_cast<const float4*>(z + (size_t)safe * D_Z)[lane];
    }

    // ---- 2) xwb partials while z is in flight.
    //      Warp w owns d in [8w, 8w+8); lane covers m = 4*lane..4*lane+3. ----
    {
        float4 acc[4] = {{0,0,0,0},{0,0,0,0},{0,0,0,0},{0,0,0,0}};
        const int d0 = warp * 8;
        #pragma unroll
        for (int i = 0; i < 8; ++i) {
            const int d = d0 + i;
            const float4 xv = x4[d * 32 + lane];             // L2-resident
            const float4 w  = W4[D_Z + d];                   // L1 broadcast
            acc[0].x = fmaf(xv.x, w.x, acc[0].x); acc[0].y = fmaf(xv.x, w.y, acc[0].y);
            acc[0].z = fmaf(xv.x, w.z, acc[0].z); acc[0].w = fmaf(xv.x, w.w, acc[0].w);
            acc[1].x = fmaf(xv.y, w.x, acc[1].x); acc[1].y = fmaf(xv.y, w.y, acc[1].y);
            acc[1].z = fmaf(xv.y, w.z, acc[1].z); acc[1].w = fmaf(xv.y, w.w, acc[1].w);
            acc[2].x = fmaf(xv.z, w.x, acc[2].x); acc[2].y = fmaf(xv.z, w.y, acc[2].y);
            acc[2].z = fmaf(xv.z, w.z, acc[2].z); acc[2].w = fmaf(xv.z, w.w, acc[2].w);
            acc[3].x = fmaf(xv.w, w.x, acc[3].x); acc[3].y = fmaf(xv.w, w.y, acc[3].y);
            acc[3].z = fmaf(xv.w, w.z, acc[3].z); acc[3].w = fmaf(xv.w, w.w, acc[3].w);
        }
        #pragma unroll
        for (int c = 0; c < 4; ++c) sPart[warp][lane * 4 + c] = acc[c];
    }

    // ---- 3) zw for 4 rows; full butterfly leaves sums in ALL lanes ----
    float4 a[4];
    {
        const float4 w0 = W4[lane * 4 + 0];
        const float4 w1 = W4[lane * 4 + 1];
        const float4 w2 = W4[lane * 4 + 2];
        const float4 w3 = W4[lane * 4 + 3];

        #pragma unroll
        for (int j = 0; j < 4; ++j) {
            float4 t;
            t.x = zv[j].x * w0.x; t.y = zv[j].x * w0.y;
            t.z = zv[j].x * w0.z; t.w = zv[j].x * w0.w;
            t.x = fmaf(zv[j].y, w1.x, t.x); t.y = fmaf(zv[j].y, w1.y, t.y);
            t.z = fmaf(zv[j].y, w1.z, t.z); t.w = fmaf(zv[j].y, w1.w, t.w);
            t.x = fmaf(zv[j].z, w2.x, t.x); t.y = fmaf(zv[j].z, w2.y, t.y);
            t.z = fmaf(zv[j].z, w2.z, t.z); t.w = fmaf(zv[j].z, w2.w, t.w);
            t.x = fmaf(zv[j].w, w3.x, t.x); t.y = fmaf(zv[j].w, w3.y, t.y);
            t.z = fmaf(zv[j].w, w3.z, t.z); t.w = fmaf(zv[j].w, w3.w, t.w);
            a[j] = t;
        }
        #pragma unroll
        for (int off = 16; off; off >>= 1) {   // 16 independent chains: ILP
            #pragma unroll
            for (int j = 0; j < 4; ++j) {
                a[j].x += __shfl_xor_sync(0xffffffffu, a[j].x, off);
                a[j].y += __shfl_xor_sync(0xffffffffu, a[j].y, off);
                a[j].z += __shfl_xor_sync(0xffffffffu, a[j].z, off);
                a[j].w += __shfl_xor_sync(0xffffffffu, a[j].w, off);
            }
        }
    }
    __syncthreads();

    // ---- 4) Fold xwb partials: 128 threads, 16-way add + bias ----
    if (tid < M_COLS) {
        float4 s = *reinterpret_cast<const float4*>(b);
        #pragma unroll
        for (int w = 0; w < NWARPS; ++w) {
            const float4 p = sPart[w][tid];
            s.x += p.x; s.y += p.y; s.z += p.z; s.w += p.w;
        }
        sXWB[tid] = s;
    }
    __syncthreads();

    // ---- 5) Stream with 256-bit stores: lane writes m = {2l,2l+1} and
    //         {64+2l, 65+2l}; warp covers contiguous 1 KB per STG.256. ----
    const float4 c0 = sXWB[2 * lane + 0];
    const float4 c1 = sXWB[2 * lane + 1];
    const float4 c2 = sXWB[2 * lane + 64];
    const float4 c3 = sXWB[2 * lane + 65];

    #pragma unroll
    for (int j = 0; j < 4; ++j) {
        if (valid[j]) {
            float4* __restrict__ o = out4 + ((size_t)rown[j] << 7);  // row*128
            float4 rA, rB;
            rA.x = fmaxf(a[j].x + c0.x, 0.f); rA.y = fmaxf(a[j].y + c0.y, 0.f);
            rA.z = fmaxf(a[j].z + c0.z, 0.f); rA.w = fmaxf(a[j].w + c0.w, 0.f);
            rB.x = fmaxf(a[j].x + c1.x, 0.f); rB.y = fmaxf(a[j].y + c1.y, 0.f);
            rB.z = fmaxf(a[j].z + c1.z, 0.f); rB.w = fmaxf(a[j].w + c1.w, 0.f);
            STG256(o + 2 * lane, rA, rB);

            rA.x = fmaxf(a[j].x + c2.x, 0.f); rA.y = fmaxf(a[j].y + c2.y, 0.f);
            rA.z = fmaxf(a[j].z + c2.z, 0.f); rA.w = fmaxf(a[j].w + c2.w, 0.f);
            rB.x = fmaxf(a[j].x + c3.x, 0.f); rB.y = fmaxf(a[j].y + c3.y, 0.f);
            rB.z = fmaxf(a[j].z + c3.z, 0.f); rB.w = fmaxf(a[j].w + c3.w, 0.f);
            STG256(o + 64 + 2 * lane, rA, rB);
        }
    }
}

extern "C" void kernel_launch(void* const* d_in, const int* in_sizes, int n_in,
                              void* d_out, int out_size)
{
    const float* z = (const float*)d_in[0];   // [8192,128]
    const float* x = (const float*)d_in[1];   // [128,128]
    const float* W = (const float*)d_in[2];   // [256,4]
    const float* b = (const float*)d_in[3];   // [4]
    float4* out4   = (float4*)d_out;

    fused_kernel<<<NBLOCKS, NTHREADS>>>(z, x, W, b, out4);
}

// round 17
// speedup vs baseline: 2.2840x; 2.2840x over previous
#include <cuda_runtime.h>

// out[n,m,:4] = relu( zw4[n] + xwb4[m] ),  zw4 = z@W1, xwb4 = x^T@W2 + b
// N=8192, M=128, DZ=DX=128, H=4.
//
// R13 skeleton (best wall: 10.72us) + ONE change: the xwb fold runs on all
// 512 threads (scalar component per thread) instead of 128 threads x float4.
// R15's STG.256 reverted: it improved profiled dur but blew up wall time.

#define N_ROWS   8192
#define M_COLS   128
#define D_Z      128
#define D_X      128
#define NBLOCKS  148
#define NTHREADS 512
#define NWARPS   (NTHREADS / 32)       // 16

__global__ __launch_bounds__(NTHREADS)
void fused_kernel(const float* __restrict__ z,
                  const float* __restrict__ x,
                  const float* __restrict__ W,
                  const float* __restrict__ b,
                  float4* __restrict__ out4)
{
    __shared__ float4 sPart[NWARPS][M_COLS];   // 32 KB xwb partials
    __shared__ float4 sXWB[M_COLS];            // 2 KB

    const int tid  = threadIdx.x;
    const int bid  = blockIdx.x;
    const int lane = tid & 31;
    const int warp = tid >> 5;                 // 0..15
    const float4* W4 = reinterpret_cast<const float4*>(W);
    const float4* x4 = reinterpret_cast<const float4*>(x);

    // Row range for this block (55/56 rows); warp owns 4 consecutive rows.
    const int r0 = (bid * N_ROWS) / NBLOCKS;
    const int r1 = ((bid + 1) * N_ROWS) / NBLOCKS;
    const int base_row = r0 + warp * 4;

    // ---- 1) Issue z loads for this warp's (up to) 4 rows first (DRAM) ----
    int   rown[4];
    bool  valid[4];
    float4 zv[4];
    #pragma unroll
    for (int j = 0; j < 4; ++j) {
        rown[j]  = base_row + j;
        valid[j] = rown[j] < r1;
        const int safe = valid[j] ? rown[j] : (r1 - 1);   // in-bounds clamp
        zv[j] = reinterpret_cast<const float4*>(z + (size_t)safe * D_Z)[lane];
    }

    // ---- 2) xwb partials while z is in flight.
    //      Warp w owns d in [8w, 8w+8); lane covers m = 4*lane..4*lane+3. ----
    {
        float4 acc[4] = {{0,0,0,0},{0,0,0,0},{0,0,0,0},{0,0,0,0}};
        const int d0 = warp * 8;
        #pragma unroll
        for (int i = 0; i < 8; ++i) {
            const int d = d0 + i;
            const float4 xv = x4[d * 32 + lane];             // L2-resident
            const float4 w  = W4[D_Z + d];                   // L1 broadcast
            acc[0].x = fmaf(xv.x, w.x, acc[0].x); acc[0].y = fmaf(xv.x, w.y, acc[0].y);
            acc[0].z = fmaf(xv.x, w.z, acc[0].z); acc[0].w = fmaf(xv.x, w.w, acc[0].w);
            acc[1].x = fmaf(xv.y, w.x, acc[1].x); acc[1].y = fmaf(xv.y, w.y, acc[1].y);
            acc[1].z = fmaf(xv.y, w.z, acc[1].z); acc[1].w = fmaf(xv.y, w.w, acc[1].w);
            acc[2].x = fmaf(xv.z, w.x, acc[2].x); acc[2].y = fmaf(xv.z, w.y, acc[2].y);
            acc[2].z = fmaf(xv.z, w.z, acc[2].z); acc[2].w = fmaf(xv.z, w.w, acc[2].w);
            acc[3].x = fmaf(xv.w, w.x, acc[3].x); acc[3].y = fmaf(xv.w, w.y, acc[3].y);
            acc[3].z = fmaf(xv.w, w.z, acc[3].z); acc[3].w = fmaf(xv.w, w.w, acc[3].w);
        }
        #pragma unroll
        for (int c = 0; c < 4; ++c) sPart[warp][lane * 4 + c] = acc[c];
    }

    // ---- 3) zw for 4 rows; full butterfly leaves sums in ALL lanes ----
    float4 a[4];
    {
        const float4 w0 = W4[lane * 4 + 0];
        const float4 w1 = W4[lane * 4 + 1];
        const float4 w2 = W4[lane * 4 + 2];
        const float4 w3 = W4[lane * 4 + 3];

        #pragma unroll
        for (int j = 0; j < 4; ++j) {
            float4 t;
            t.x = zv[j].x * w0.x; t.y = zv[j].x * w0.y;
            t.z = zv[j].x * w0.z; t.w = zv[j].x * w0.w;
            t.x = fmaf(zv[j].y, w1.x, t.x); t.y = fmaf(zv[j].y, w1.y, t.y);
            t.z = fmaf(zv[j].y, w1.z, t.z); t.w = fmaf(zv[j].y, w1.w, t.w);
            t.x = fmaf(zv[j].z, w2.x, t.x); t.y = fmaf(zv[j].z, w2.y, t.y);
            t.z = fmaf(zv[j].z, w2.z, t.z); t.w = fmaf(zv[j].z, w2.w, t.w);
            t.x = fmaf(zv[j].w, w3.x, t.x); t.y = fmaf(zv[j].w, w3.y, t.y);
            t.z = fmaf(zv[j].w, w3.z, t.z); t.w = fmaf(zv[j].w, w3.w, t.w);
            a[j] = t;
        }
        #pragma unroll
        for (int off = 16; off; off >>= 1) {   // 16 independent chains: ILP
            #pragma unroll
            for (int j = 0; j < 4; ++j) {
                a[j].x += __shfl_xor_sync(0xffffffffu, a[j].x, off);
                a[j].y += __shfl_xor_sync(0xffffffffu, a[j].y, off);
                a[j].z += __shfl_xor_sync(0xffffffffu, a[j].z, off);
                a[j].w += __shfl_xor_sync(0xffffffffu, a[j].w, off);
            }
        }
    }
    __syncthreads();

    // ---- 4) Fold xwb partials on ALL 512 threads: thread t folds
    //      component (t&3) of m = (t>>2). Scalar LDS, conflict-free. ----
    {
        const int m = tid >> 2;                // 0..127
        const int c = tid & 3;                 // component
        const float* pp = reinterpret_cast<const float*>(&sPart[0][m]) + c;
        float s = b[c];
        #pragma unroll
        for (int w = 0; w < NWARPS; ++w)
            s += pp[w * M_COLS * 4];           // stride = one sPart row in floats
        reinterpret_cast<float*>(&sXWB[m])[c] = s;
    }
    __syncthreads();

    // ---- 5) Stream straight from registers: up to 16 STG.128/thread ----
    const float4 c0 = sXWB[lane];
    const float4 c1 = sXWB[lane + 32];
    const float4 c2 = sXWB[lane + 64];
    const float4 c3 = sXWB[lane + 96];

    #pragma unroll
    for (int j = 0; j < 4; ++j) {
        if (valid[j]) {
            float4* __restrict__ o = out4 + ((size_t)rown[j] << 7);  // row*128
            float4 r;
            r.x = fmaxf(a[j].x + c0.x, 0.f); r.y = fmaxf(a[j].y + c0.y, 0.f);
            r.z = fmaxf(a[j].z + c0.z, 0.f); r.w = fmaxf(a[j].w + c0.w, 0.f);
            o[lane] = r;
            r.x = fmaxf(a[j].x + c1.x, 0.f); r.y = fmaxf(a[j].y + c1.y, 0.f);
            r.z = fmaxf(a[j].z + c1.z, 0.f); r.w = fmaxf(a[j].w + c1.w, 0.f);
            o[lane + 32] = r;
            r.x = fmaxf(a[j].x + c2.x, 0.f); r.y = fmaxf(a[j].y + c2.y, 0.f);
            r.z = fmaxf(a[j].z + c2.z, 0.f); r.w = fmaxf(a[j].w + c2.w, 0.f);
            o[lane + 64] = r;
            r.x = fmaxf(a[j].x + c3.x, 0.f); r.y = fmaxf(a[j].y + c3.y, 0.f);
            r.z = fmaxf(a[j].z + c3.z, 0.f); r.w = fmaxf(a[j].w + c3.w, 0.f);
            o[lane + 96] = r;
        }
    }
}

extern "C" void kernel_launch(void* const* d_in, const int* in_sizes, int n_in,
                              void* d_out, int out_size)
{
    const float* z = (const float*)d_in[0];   // [8192,128]
    const float* x = (const float*)d_in[1];   // [128,128]
    const float* W = (const float*)d_in[2];   // [256,4]
    const float* b = (const float*)d_in[3];   // [4]
    float4* out4   = (float4*)d_out;

    fused_kernel<<<NBLOCKS, NTHREADS>>>(z, x, W, b, out4);
}